// round 1
// baseline (speedup 1.0000x reference)
#include <cuda_runtime.h>
#include <stdint.h>

#define Bb 32
#define Nn 512
#define Ll 8
#define Kk 8
#define MS 64   // max distinct indices per batch (L*K)

// ---------------- scratch (static device globals; no runtime allocation) ----
__device__ float  g_M[Bb][MS][MS];        // right restricted to R x R block
__device__ float  g_DRR[Bb][MS][MS];      // masked M A_RR M^T
__device__ float  g_G2[Bb][MS][MS];       // M^T D_RR M
__device__ float  g_Drow[Bb][MS][Nn];     // D strip rows (rows in R)
__device__ float  g_Arow[Bb][MS][Nn];     // A_rec strip rows
__device__ float  g_DcolT[Bb][Nn][MS];    // g_Drow transposed: [c][slot]
__device__ float  g_AcolT[Bb][Nn][MS];
__device__ int8_t g_slotof[Bb][Nn];       // global index -> slot (or -1)
__device__ int    g_slots[Bb][MS];
__device__ int8_t g_wflag[Bb][MS];

// ---------------- K1: per-batch setup (M, corner matrices) ------------------
// dyn smem: Msh[64*64] T1[64*64] T2[64*64] tmp[8*64] f32 | slotof[512] slots[64] wflag[64] int
#define K1_SMEM ((4096*3 + 512)*4 + (512+64+64)*4)

__global__ void mmf_k1(const float* __restrict__ A, const float* __restrict__ O,
                       const int* __restrict__ idx, const int* __restrict__ wav) {
    extern __shared__ char sm1[];
    float* Msh = (float*)sm1;
    float* T1  = Msh + 4096;
    float* T2  = T1 + 4096;
    float* tmp = T2 + 4096;                 // 8*64
    int* slotof = (int*)(tmp + Kk*64);      // 512
    int* slots  = slotof + Nn;              // 64
    int* wflag  = slots + MS;               // 64

    const int b = blockIdx.x;
    const int tid = threadIdx.x;            // 256 threads

    for (int j = tid; j < Nn; j += blockDim.x) slotof[j] = -1;
    for (int j = tid; j < MS; j += blockDim.x) { wflag[j] = 0; slots[j] = 0; }
    __syncthreads();

    if (tid == 0) {
        int m = 0;
        for (int l = 0; l < Ll; l++)
            for (int k = 0; k < Kk; k++) {
                int g = idx[(b*Ll + l)*Kk + k];
                if (slotof[g] < 0) { slotof[g] = m; slots[m] = g; m++; }
            }
        for (int l = 0; l < Ll; l++) {
            int w = wav[b*Ll + l];
            wflag[slotof[w]] = 1;
        }
    }
    __syncthreads();

    // M = I
    for (int e = tid; e < 4096; e += blockDim.x)
        Msh[e] = ((e >> 6) == (e & 63)) ? 1.f : 0.f;
    __syncthreads();

    // layer updates: rows slot(idx_l) <- O_l @ rows slot(idx_l)
    __shared__ int   rs[Kk];
    __shared__ float Osh[Kk*Kk];
    for (int l = 0; l < Ll; l++) {
        if (tid < Kk) rs[tid] = slotof[idx[(b*Ll + l)*Kk + tid]];
        if (tid < Kk*Kk) Osh[tid] = O[((size_t)l*Bb + b)*Kk*Kk + tid];
        __syncthreads();
        for (int e = tid; e < Kk*64; e += blockDim.x) {
            int i = e >> 6, c = e & 63;
            float s = 0.f;
            #pragma unroll
            for (int j = 0; j < Kk; j++) s += Osh[i*Kk + j] * Msh[rs[j]*64 + c];
            tmp[e] = s;
        }
        __syncthreads();
        for (int e = tid; e < Kk*64; e += blockDim.x)
            Msh[rs[e >> 6]*64 + (e & 63)] = tmp[e];
        __syncthreads();
    }

    // publish M + maps
    for (int e = tid; e < 4096; e += blockDim.x) g_M[b][e >> 6][e & 63] = Msh[e];
    for (int j = tid; j < Nn; j += blockDim.x) g_slotof[b][j] = (int8_t)slotof[j];
    for (int j = tid; j < MS; j += blockDim.x) {
        g_slots[b][j] = slots[j];
        g_wflag[b][j] = (int8_t)wflag[j];
    }

    // T1 = A_RR (gather)
    for (int e = tid; e < 4096; e += blockDim.x) {
        int i = e >> 6, j = e & 63;
        T1[e] = A[((size_t)b*Nn + slots[i])*Nn + slots[j]];
    }
    __syncthreads();
    // T2 = M @ T1
    for (int e = tid; e < 4096; e += blockDim.x) {
        int i = e >> 6, j = e & 63;
        float s = 0.f;
        #pragma unroll 8
        for (int k = 0; k < 64; k++) s += Msh[i*64 + k] * T1[k*64 + j];
        T2[e] = s;
    }
    __syncthreads();
    // T1 = T2 @ M^T   (= F_RR = M A_RR M^T)
    for (int e = tid; e < 4096; e += blockDim.x) {
        int i = e >> 6, j = e & 63;
        float s = 0.f;
        #pragma unroll 8
        for (int k = 0; k < 64; k++) s += T2[i*64 + k] * Msh[j*64 + k];
        T1[e] = s;
    }
    __syncthreads();
    // D_RR = mask(F_RR): zero rows/cols in W, keep diagonal
    for (int e = tid; e < 4096; e += blockDim.x) {
        int i = e >> 6, j = e & 63;
        float v = T1[e];
        if (i != j && (wflag[i] || wflag[j])) v = 0.f;
        T1[e] = v;
        g_DRR[b][i][j] = v;
    }
    __syncthreads();
    // T2 = M^T @ D_RR
    for (int e = tid; e < 4096; e += blockDim.x) {
        int i = e >> 6, j = e & 63;
        float s = 0.f;
        #pragma unroll 8
        for (int k = 0; k < 64; k++) s += Msh[k*64 + i] * T1[k*64 + j];
        T2[e] = s;
    }
    __syncthreads();
    // G2 = T2 @ M
    for (int e = tid; e < 4096; e += blockDim.x) {
        int i = e >> 6, j = e & 63;
        float s = 0.f;
        #pragma unroll 8
        for (int k = 0; k < 64; k++) s += T2[i*64 + k] * Msh[k*64 + j];
        g_G2[b][i][j] = s;
    }
}

// ---------------- K2: strip GEMMs per 64-column tile -----------------------
// dyn smem: Msh[64*64], ARt[64*65], Ft[64*65]
#define K2_SMEM ((4096 + 64*65*2)*4)

__global__ void mmf_k2(const float* __restrict__ A) {
    extern __shared__ char sm2[];
    float* Msh = (float*)sm2;
    float* ARt = Msh + 4096;        // 64 x 65 (padded)
    float* Ft  = ARt + 64*65;

    __shared__ int    slots[MS];
    __shared__ int8_t wfl[MS];
    __shared__ int8_t slc[64];

    const int b  = blockIdx.y;
    const int c0 = blockIdx.x * 64;
    const int tid = threadIdx.x;    // 256

    for (int e = tid; e < 4096; e += 256) Msh[e] = g_M[b][e >> 6][e & 63];
    if (tid < 64) {
        slots[tid] = g_slots[b][tid];
        wfl[tid]   = g_wflag[b][tid];
        slc[tid]   = g_slotof[b][c0 + tid];
    }
    __syncthreads();

    // gather A rows (A_R tile)
    for (int e = tid; e < 4096; e += 256) {
        int k = e >> 6, c = e & 63;
        ARt[k*65 + c] = A[((size_t)b*Nn + slots[k])*Nn + c0 + c];
    }
    __syncthreads();

    const int c  = tid & 63;
    const int ig = tid >> 6;        // 0..3
    const int sc = slc[c];

    // F tile = M @ A_R tile
    float acc[16];
    #pragma unroll
    for (int r = 0; r < 16; r++) {
        int i = ig + 4*r;
        float s = 0.f;
        #pragma unroll 8
        for (int k = 0; k < 64; k++) s += Msh[i*64 + k] * ARt[k*65 + c];
        acc[r] = s;
    }
    __syncthreads();

    // Drow tile (mask / corner substitution) -> overwrite ARt, write global
    #pragma unroll
    for (int r = 0; r < 16; r++) {
        int i = ig + 4*r;
        float v = (sc >= 0) ? g_DRR[b][i][sc] : (wfl[i] ? 0.f : acc[r]);
        ARt[i*65 + c] = v;
        g_Drow[b][i][c0 + c] = v;
    }
    __syncthreads();

    // coalesced transposed copy
    for (int e = tid; e < 4096; e += 256) {
        int cc = e >> 6, i = e & 63;
        g_DcolT[b][c0 + cc][i] = ARt[i*65 + cc];
    }

    // E tile = M^T @ Drow tile ; A_rec strip with corner substitution
    #pragma unroll
    for (int r = 0; r < 16; r++) {
        int i = ig + 4*r;
        float s = 0.f;
        #pragma unroll 8
        for (int k = 0; k < 64; k++) s += Msh[k*64 + i] * ARt[k*65 + c];
        float v = (sc >= 0) ? g_G2[b][i][sc] : s;
        Ft[i*65 + c] = v;
        g_Arow[b][i][c0 + c] = v;
    }
    __syncthreads();

    for (int e = tid; e < 4096; e += 256) {
        int cc = e >> 6, i = e & 63;
        g_AcolT[b][c0 + cc][i] = Ft[i*65 + cc];
    }
}

// ---------------- K3: single-pass assembly (bandwidth-bound) ---------------
__global__ void __launch_bounds__(512) mmf_k3(const float* __restrict__ A,
                                              float* __restrict__ out) {
    const int b    = blockIdx.y;
    const int i    = blockIdx.x * 4 + (threadIdx.x >> 7);
    const int lane = threadIdx.x & 127;
    const int c0   = lane * 4;

    const int srow = g_slotof[b][i];
    const size_t rowbase = ((size_t)b*Nn + i)*Nn + c0;
    const char4 sl = *(const char4*)(&g_slotof[b][c0]);

    float4 va, vd, vr;
    if (srow >= 0) {
        va = *(const float4*)(&g_Arow[b][srow][c0]);
        vd = *(const float4*)(&g_Drow[b][srow][c0]);
        const float* Mr = &g_M[b][srow][0];
        vr.x = (sl.x >= 0) ? Mr[sl.x] : 0.f;
        vr.y = (sl.y >= 0) ? Mr[sl.y] : 0.f;
        vr.z = (sl.z >= 0) ? Mr[sl.z] : 0.f;
        vr.w = (sl.w >= 0) ? Mr[sl.w] : 0.f;
    } else {
        float4 a = *(const float4*)(&A[rowbase]);
        va = a; vd = a;
        const float* act = &g_AcolT[b][i][0];
        const float* dct = &g_DcolT[b][i][0];
        if (sl.x >= 0) { va.x = act[sl.x]; vd.x = dct[sl.x]; }
        if (sl.y >= 0) { va.y = act[sl.y]; vd.y = dct[sl.y]; }
        if (sl.z >= 0) { va.z = act[sl.z]; vd.z = dct[sl.z]; }
        if (sl.w >= 0) { va.w = act[sl.w]; vd.w = dct[sl.w]; }
        vr = make_float4(0.f, 0.f, 0.f, 0.f);
        if (i >= c0 && i < c0 + 4) ((float*)&vr)[i - c0] = 1.f;
    }

    const size_t MAT = (size_t)Bb * Nn * Nn;
    *(float4*)(&out[rowbase])           = va;   // A_rec
    *(float4*)(&out[MAT + rowbase])     = vr;   // right
    *(float4*)(&out[2*MAT + rowbase])   = vd;   // D
}

// ---------------- launch ----------------------------------------------------
extern "C" void kernel_launch(void* const* d_in, const int* in_sizes, int n_in,
                              void* d_out, int out_size) {
    const float* A   = (const float*)d_in[0];
    const float* O   = (const float*)d_in[1];
    const int*   idx = (const int*)d_in[2];
    const int*   wav = (const int*)d_in[3];
    float* out = (float*)d_out;

    cudaFuncSetAttribute(mmf_k1, cudaFuncAttributeMaxDynamicSharedMemorySize, K1_SMEM);
    cudaFuncSetAttribute(mmf_k2, cudaFuncAttributeMaxDynamicSharedMemorySize, K2_SMEM);

    mmf_k1<<<Bb, 256, K1_SMEM>>>(A, O, idx, wav);
    mmf_k2<<<dim3(Nn/64, Bb), 256, K2_SMEM>>>(A);
    mmf_k3<<<dim3(Nn/4, Bb), 512>>>(A, out);
}

// round 2
// speedup vs baseline: 1.4950x; 1.4950x over previous
#include <cuda_runtime.h>
#include <stdint.h>

#define Bb 32
#define Nn 512
#define Ll 8
#define Kk 8
#define MS 64
#define SP 68   // shared stride: 68%32=4 -> conflict-free column access; 68*4B%16=0 -> LDS.128 OK

// ---------------- scratch (static device globals) ---------------------------
__device__ float  g_M[Bb][MS][MS];
__device__ float  g_MT[Bb][MS][MS];
__device__ float  g_DRR[Bb][MS][MS];
__device__ float  g_G2[Bb][MS][MS];
__device__ float  g_Drow[Bb][MS][Nn];
__device__ float  g_Arow[Bb][MS][Nn];
__device__ float  g_DcolT[Bb][Nn][MS];
__device__ float  g_AcolT[Bb][Nn][MS];
__device__ int8_t g_slotof[Bb][Nn];
__device__ int    g_slots[Bb][MS];
__device__ int8_t g_wflag[Bb][MS];

// ---------------- packed f32x2 helpers --------------------------------------
typedef unsigned long long ull;

__device__ __forceinline__ ull pack2(float x) {
    ull r; asm("mov.b64 %0, {%1, %1};" : "=l"(r) : "f"(x)); return r;
}
__device__ __forceinline__ void ffma2(ull& d, ull a, ull b) {
    asm("fma.rn.f32x2 %0, %1, %2, %3;" : "=l"(d) : "l"(a), "l"(b), "l"(d));
}

// C = A @ B, all 64x64 with stride SP in shared. 256 threads.
// thread: 2 rows x 8 cols. tx=tid&7 -> j0=8*tx ; ty=tid>>3 -> i0=2*ty.
__device__ __forceinline__ void gemm64(const float* __restrict__ Am,
                                       const float* __restrict__ Bm,
                                       float* __restrict__ Cm, int tid) {
    const int tx = tid & 7, ty = tid >> 3;
    const int i0 = ty * 2, j0 = tx * 8;
    ull acc[2][4];
    #pragma unroll
    for (int r = 0; r < 2; r++)
        #pragma unroll
        for (int c = 0; c < 4; c++) acc[r][c] = 0ULL;

    #pragma unroll 4
    for (int k = 0; k < 64; k++) {
        ull pa0 = pack2(Am[i0 * SP + k]);
        ull pa1 = pack2(Am[(i0 + 1) * SP + k]);
        ulonglong2 b01 = *(const ulonglong2*)&Bm[k * SP + j0];
        ulonglong2 b23 = *(const ulonglong2*)&Bm[k * SP + j0 + 4];
        ffma2(acc[0][0], pa0, b01.x); ffma2(acc[0][1], pa0, b01.y);
        ffma2(acc[0][2], pa0, b23.x); ffma2(acc[0][3], pa0, b23.y);
        ffma2(acc[1][0], pa1, b01.x); ffma2(acc[1][1], pa1, b01.y);
        ffma2(acc[1][2], pa1, b23.x); ffma2(acc[1][3], pa1, b23.y);
    }
    #pragma unroll
    for (int r = 0; r < 2; r++) {
        ulonglong2 s0; s0.x = acc[r][0]; s0.y = acc[r][1];
        ulonglong2 s1; s1.x = acc[r][2]; s1.y = acc[r][3];
        *(ulonglong2*)&Cm[(i0 + r) * SP + j0]     = s0;
        *(ulonglong2*)&Cm[(i0 + r) * SP + j0 + 4] = s1;
    }
}

// ---------------- K1: per-batch setup ---------------------------------------
// smem floats: Msh,MTsh,T1,T2 (64*SP each) + tmp(512) ; ints: slotof(512)+slots(64)+wflag(64)
#define K1_SMEM ((4*64*SP + 512)*4 + (512+64+64)*4)

__global__ void __launch_bounds__(256) mmf_k1(const float* __restrict__ A,
                                              const float* __restrict__ O,
                                              const int* __restrict__ idx,
                                              const int* __restrict__ wav) {
    extern __shared__ float sm[];
    float* Msh  = sm;
    float* MTsh = sm + 64 * SP;
    float* T1   = sm + 2 * 64 * SP;
    float* T2   = sm + 3 * 64 * SP;
    float* tmp  = sm + 4 * 64 * SP;          // 8*64
    int* slotof = (int*)(tmp + 512);
    int* slots  = slotof + Nn;
    int* wflag  = slots + MS;

    const int b = blockIdx.x;
    const int tid = threadIdx.x;

    for (int j = tid; j < Nn; j += 256) slotof[j] = -1;
    for (int j = tid; j < MS; j += 256) { wflag[j] = 0; slots[j] = 0; }
    __syncthreads();

    if (tid == 0) {
        int m = 0;
        for (int l = 0; l < Ll; l++)
            for (int k = 0; k < Kk; k++) {
                int g = idx[(b * Ll + l) * Kk + k];
                if (slotof[g] < 0) { slotof[g] = m; slots[m] = g; m++; }
            }
        for (int l = 0; l < Ll; l++) wflag[slotof[wav[b * Ll + l]]] = 1;
    }
    __syncthreads();

    // M = I
    for (int e = tid; e < 4096; e += 256) {
        int i = e >> 6, j = e & 63;
        Msh[i * SP + j] = (i == j) ? 1.f : 0.f;
    }
    __syncthreads();

    // layer updates
    __shared__ int   rs[Kk];
    __shared__ float Osh[Kk * Kk];
    for (int l = 0; l < Ll; l++) {
        if (tid < Kk) rs[tid] = slotof[idx[(b * Ll + l) * Kk + tid]];
        if (tid < Kk * Kk) Osh[tid] = O[((size_t)l * Bb + b) * Kk * Kk + tid];
        __syncthreads();
        for (int e = tid; e < Kk * 64; e += 256) {
            int i = e >> 6, c = e & 63;
            float s = 0.f;
            #pragma unroll
            for (int j = 0; j < Kk; j++) s += Osh[i * Kk + j] * Msh[rs[j] * SP + c];
            tmp[e] = s;
        }
        __syncthreads();
        for (int e = tid; e < Kk * 64; e += 256)
            Msh[rs[e >> 6] * SP + (e & 63)] = tmp[e];
        __syncthreads();
    }

    // MT + publish
    for (int e = tid; e < 4096; e += 256) {
        int i = e >> 6, j = e & 63;
        float v = Msh[i * SP + j];
        MTsh[j * SP + i] = v;
        g_M[b][i][j] = v;
    }
    for (int j = tid; j < Nn; j += 256) g_slotof[b][j] = (int8_t)slotof[j];
    for (int j = tid; j < MS; j += 256) {
        g_slots[b][j] = slots[j];
        g_wflag[b][j] = (int8_t)wflag[j];
    }
    __syncthreads();
    for (int e = tid; e < 4096; e += 256) {
        int i = e >> 6, j = e & 63;
        g_MT[b][i][j] = MTsh[i * SP + j];
    }

    // T1 = A_RR gather
    for (int e = tid; e < 4096; e += 256) {
        int i = e >> 6, j = e & 63;
        T1[i * SP + j] = A[((size_t)b * Nn + slots[i]) * Nn + slots[j]];
    }
    __syncthreads();

    gemm64(Msh, T1, T2, tid);   __syncthreads();   // T2 = M A_RR
    gemm64(T2, MTsh, T1, tid);  __syncthreads();   // T1 = M A_RR M^T

    // mask -> D_RR
    for (int e = tid; e < 4096; e += 256) {
        int i = e >> 6, j = e & 63;
        float v = T1[i * SP + j];
        if (i != j && (wflag[i] || wflag[j])) v = 0.f;
        T1[i * SP + j] = v;
        g_DRR[b][i][j] = v;
    }
    __syncthreads();

    gemm64(MTsh, T1, T2, tid);  __syncthreads();   // T2 = M^T D_RR
    gemm64(T2, Msh, T1, tid);   __syncthreads();   // T1 = G2 = M^T D_RR M

    for (int e = tid; e < 4096; e += 256) {
        int i = e >> 6, j = e & 63;
        g_G2[b][i][j] = T1[i * SP + j];
    }
}

// ---------------- K2: strip GEMMs per 64-col tile ---------------------------
#define K2_SMEM (4*64*SP*4)

__global__ void __launch_bounds__(256) mmf_k2(const float* __restrict__ A) {
    extern __shared__ float sm2[];
    float* Msh  = sm2;                 // then reused as E staging
    float* MTsh = sm2 + 64 * SP;
    float* Tin  = sm2 + 2 * 64 * SP;   // A_R tile, then E tile
    float* Td   = sm2 + 3 * 64 * SP;   // D tile

    __shared__ int    slots[MS];
    __shared__ int8_t wfl[MS];
    __shared__ int8_t slc[64];

    const int b  = blockIdx.y;
    const int c0 = blockIdx.x * 64;
    const int tid = threadIdx.x;

    for (int e = tid; e < 4096; e += 256) {
        int i = e >> 6, j = e & 63;
        Msh[i * SP + j]  = g_M[b][i][j];
        MTsh[i * SP + j] = g_MT[b][i][j];
    }
    if (tid < 64) {
        slots[tid] = g_slots[b][tid];
        wfl[tid]   = g_wflag[b][tid];
        slc[tid]   = g_slotof[b][c0 + tid];
    }
    __syncthreads();

    // gather A strip tile
    {
        const int k = tid >> 2, c = (tid & 3) * 16;   // 4 float4 per thread
        #pragma unroll
        for (int q = 0; q < 4; q++) {
            float4 v = *(const float4*)&A[((size_t)b * Nn + slots[k]) * Nn + c0 + c + q * 4];
            *(float4*)&Tin[k * SP + c + q * 4] = v;
        }
    }
    __syncthreads();

    gemm64(Msh, Tin, Td, tid);   // F tile = M @ A_R
    __syncthreads();

    // mask / corner substitute -> D tile; write g_Drow
    for (int e = tid; e < 4096; e += 256) {
        int i = e >> 6, c = e & 63;
        float v = Td[i * SP + c];
        int sc = slc[c];
        v = (sc >= 0) ? g_DRR[b][i][sc] : (wfl[i] ? 0.f : v);
        Td[i * SP + c] = v;
        g_Drow[b][i][c0 + c] = v;
    }
    __syncthreads();

    gemm64(MTsh, Td, Tin, tid);  // E tile = M^T @ D tile
    __syncthreads();

    // corner substitute -> A_rec strip; write g_Arow
    for (int e = tid; e < 4096; e += 256) {
        int i = e >> 6, c = e & 63;
        float v = Tin[i * SP + c];
        int sc = slc[c];
        v = (sc >= 0) ? g_G2[b][i][sc] : v;
        Tin[i * SP + c] = v;
        g_Arow[b][i][c0 + c] = v;
    }
    __syncthreads();

    // coalesced transposed copies
    for (int e = tid; e < 4096; e += 256) {
        int cc = e >> 6, i = e & 63;
        g_DcolT[b][c0 + cc][i] = Td[i * SP + cc];
        g_AcolT[b][c0 + cc][i] = Tin[i * SP + cc];
    }
}

// ---------------- K3: single-pass assembly ----------------------------------
__global__ void __launch_bounds__(512) mmf_k3(const float* __restrict__ A,
                                              float* __restrict__ out) {
    const int b    = blockIdx.y;
    const int i    = blockIdx.x * 4 + (threadIdx.x >> 7);
    const int lane = threadIdx.x & 127;
    const int c0   = lane * 4;

    const int srow = g_slotof[b][i];
    const size_t rowbase = ((size_t)b * Nn + i) * Nn + c0;
    const char4 sl = *(const char4*)(&g_slotof[b][c0]);

    float4 va, vd, vr;
    if (srow >= 0) {
        va = *(const float4*)(&g_Arow[b][srow][c0]);
        vd = *(const float4*)(&g_Drow[b][srow][c0]);
        const float* Mr = &g_M[b][srow][0];
        vr.x = (sl.x >= 0) ? Mr[sl.x] : 0.f;
        vr.y = (sl.y >= 0) ? Mr[sl.y] : 0.f;
        vr.z = (sl.z >= 0) ? Mr[sl.z] : 0.f;
        vr.w = (sl.w >= 0) ? Mr[sl.w] : 0.f;
    } else {
        float4 a = *(const float4*)(&A[rowbase]);
        va = a; vd = a;
        const float* act = &g_AcolT[b][i][0];
        const float* dct = &g_DcolT[b][i][0];
        if (sl.x >= 0) { va.x = act[sl.x]; vd.x = dct[sl.x]; }
        if (sl.y >= 0) { va.y = act[sl.y]; vd.y = dct[sl.y]; }
        if (sl.z >= 0) { va.z = act[sl.z]; vd.z = dct[sl.z]; }
        if (sl.w >= 0) { va.w = act[sl.w]; vd.w = dct[sl.w]; }
        vr = make_float4(0.f, 0.f, 0.f, 0.f);
        if (i >= c0 && i < c0 + 4) ((float*)&vr)[i - c0] = 1.f;
    }

    const size_t MAT = (size_t)Bb * Nn * Nn;
    *(float4*)(&out[rowbase])         = va;
    *(float4*)(&out[MAT + rowbase])   = vr;
    *(float4*)(&out[2 * MAT + rowbase]) = vd;
}

// ---------------- launch -----------------------------------------------------
extern "C" void kernel_launch(void* const* d_in, const int* in_sizes, int n_in,
                              void* d_out, int out_size) {
    const float* A   = (const float*)d_in[0];
    const float* O   = (const float*)d_in[1];
    const int*   idx = (const int*)d_in[2];
    const int*   wav = (const int*)d_in[3];
    float* out = (float*)d_out;

    cudaFuncSetAttribute(mmf_k1, cudaFuncAttributeMaxDynamicSharedMemorySize, K1_SMEM);
    cudaFuncSetAttribute(mmf_k2, cudaFuncAttributeMaxDynamicSharedMemorySize, K2_SMEM);

    mmf_k1<<<Bb, 256, K1_SMEM>>>(A, O, idx, wav);
    mmf_k2<<<dim3(Nn / 64, Bb), 256, K2_SMEM>>>(A);
    mmf_k3<<<dim3(Nn / 4, Bb), 512>>>(A, out);
}